// round 7
// baseline (speedup 1.0000x reference)
#include <cuda_runtime.h>
#include <cuda_fp16.h>
#include <cstdint>

// Problem dims (fixed by the dataset)
#define T_DIM 2048
#define O_DIM 4096
#define I_DIM 4096
#define R_DIM 16
#define QB    32

// Scratch: fp16 copies of W (dequant + LoRA folded) and x.
__device__ __align__(16) __half g_Wh[(size_t)O_DIM * I_DIM]; // 32 MB
__device__ __align__(16) __half g_Xh[(size_t)T_DIM * I_DIM]; // 16 MB

// ---------------------------------------------------------------------------
// Kernel 1: x (fp32) -> fp16
// ---------------------------------------------------------------------------
__global__ void cvt_x_kernel(const float* __restrict__ x) {
    size_t i = ((size_t)blockIdx.x * blockDim.x + threadIdx.x) * 4;
    float4 v = *(const float4*)(x + i);
    __half2 h0 = __floats2half2_rn(v.x, v.y);
    __half2 h1 = __floats2half2_rn(v.z, v.w);
    *(__half2*)(g_Xh + i)     = h0;
    *(__half2*)(g_Xh + i + 2) = h1;
}

// ---------------------------------------------------------------------------
// Kernel 2: W_fp16[o,i] = (q[o,i]-8)*scale[o,i/32] + alpha * sum_r up[o,r]*down[r,i]
// Each thread: 4 consecutive i, 8 consecutive o (amortizes down[] reads 8x).
// ---------------------------------------------------------------------------
__global__ void prep_w_kernel(const int* __restrict__ q,
                              const float* __restrict__ scales,
                              const float* __restrict__ up,
                              const float* __restrict__ down,
                              const float* __restrict__ alpha_p) {
    const int igroups = I_DIM / 4; // 1024
    size_t gt = (size_t)blockIdx.x * blockDim.x + threadIdx.x;
    int ig = (int)(gt % igroups);
    int ob = (int)(gt / igroups) * 8;
    int i  = ig * 4;
    float alpha = *alpha_p;

    float4 dsum[8];
#pragma unroll
    for (int j = 0; j < 8; ++j) dsum[j] = make_float4(0.f, 0.f, 0.f, 0.f);

#pragma unroll
    for (int r = 0; r < R_DIM; ++r) {
        float4 dv = *(const float4*)(down + (size_t)r * I_DIM + i);
#pragma unroll
        for (int j = 0; j < 8; ++j) {
            float u = up[(size_t)(ob + j) * R_DIM + r];
            dsum[j].x += u * dv.x;
            dsum[j].y += u * dv.y;
            dsum[j].z += u * dv.z;
            dsum[j].w += u * dv.w;
        }
    }

#pragma unroll
    for (int j = 0; j < 8; ++j) {
        int o = ob + j;
        size_t base = (size_t)o * I_DIM + i;
        int4 qv = *(const int4*)(q + base);
        float s = scales[(size_t)o * (I_DIM / QB) + (i >> 5)];
        float w0 = (float)(qv.x - 8) * s + alpha * dsum[j].x;
        float w1 = (float)(qv.y - 8) * s + alpha * dsum[j].y;
        float w2 = (float)(qv.z - 8) * s + alpha * dsum[j].z;
        float w3 = (float)(qv.w - 8) * s + alpha * dsum[j].w;
        *(__half2*)(g_Wh + base)     = __floats2half2_rn(w0, w1);
        *(__half2*)(g_Wh + base + 2) = __floats2half2_rn(w2, w3);
    }
}

// ---------------------------------------------------------------------------
// Kernel 3: GEMM  y[t,o] = sum_k Xh[t,k]*Wh[o,k] + bias[o]   (fp16 in, fp32 acc)
// 128x128x32 CTA tile, 8 warps (2M x 4N), warp tile 64x32,
// mma.sync.m16n8k16 + ldmatrix, padded smem (stride 40 halves = conflict-free),
// double-buffered with register prefetch.
// ---------------------------------------------------------------------------
constexpr int BM = 128, BN = 128, BK = 32;
constexpr int LDS_H = BK + 8; // 40 halves per smem row (80B stride)

__device__ __forceinline__ uint32_t smem_u32(const void* p) {
    return (uint32_t)__cvta_generic_to_shared(p);
}
__device__ __forceinline__ void ldsm_x4(uint32_t* r, uint32_t addr) {
    asm volatile("ldmatrix.sync.aligned.m8n8.x4.shared.b16 {%0,%1,%2,%3}, [%4];"
                 : "=r"(r[0]), "=r"(r[1]), "=r"(r[2]), "=r"(r[3]) : "r"(addr));
}
__device__ __forceinline__ void ldsm_x2(uint32_t* r, uint32_t addr) {
    asm volatile("ldmatrix.sync.aligned.m8n8.x2.shared.b16 {%0,%1}, [%2];"
                 : "=r"(r[0]), "=r"(r[1]) : "r"(addr));
}
__device__ __forceinline__ void mma_16816(float* c, const uint32_t* a, const uint32_t* b) {
    asm volatile(
        "mma.sync.aligned.m16n8k16.row.col.f32.f16.f16.f32 "
        "{%0,%1,%2,%3}, {%4,%5,%6,%7}, {%8,%9}, {%0,%1,%2,%3};\n"
        : "+f"(c[0]), "+f"(c[1]), "+f"(c[2]), "+f"(c[3])
        : "r"(a[0]), "r"(a[1]), "r"(a[2]), "r"(a[3]), "r"(b[0]), "r"(b[1]));
}

__global__ void __launch_bounds__(256) gemm_kernel(const float* __restrict__ bias,
                                                   float* __restrict__ y) {
    __shared__ __half As[2][BM][LDS_H];
    __shared__ __half Bs[2][BN][LDS_H];

    const int tid  = threadIdx.x;
    const int lane = tid & 31;
    const int warp = tid >> 5;
    const int wm = warp >> 2; // 0..1  (M)
    const int wn = warp & 3;  // 0..3  (N)

    const size_t bmOff = (size_t)blockIdx.y * BM;
    const size_t bnOff = (size_t)blockIdx.x * BN;

    const __half* gA = g_Xh + bmOff * I_DIM;
    const __half* gB = g_Wh + bnOff * I_DIM;

    // Global->smem mapping: thread loads rows lr and lr+64, 16B chunk lc.
    const int lr = tid >> 2;       // 0..63
    const int lc = (tid & 3) * 8;  // half offset {0,8,16,24}

    float acc[4][4][4];
#pragma unroll
    for (int a = 0; a < 4; ++a)
#pragma unroll
        for (int b = 0; b < 4; ++b)
#pragma unroll
            for (int c = 0; c < 4; ++c) acc[a][b][c] = 0.f;

    uint4 ra0, ra1, rb0, rb1;
    // preload tile 0
    ra0 = *(const uint4*)(gA + (size_t)lr * I_DIM + lc);
    ra1 = *(const uint4*)(gA + (size_t)(lr + 64) * I_DIM + lc);
    rb0 = *(const uint4*)(gB + (size_t)lr * I_DIM + lc);
    rb1 = *(const uint4*)(gB + (size_t)(lr + 64) * I_DIM + lc);
    *(uint4*)(&As[0][lr][lc])      = ra0;
    *(uint4*)(&As[0][lr + 64][lc]) = ra1;
    *(uint4*)(&Bs[0][lr][lc])      = rb0;
    *(uint4*)(&Bs[0][lr + 64][lc]) = rb1;
    __syncthreads();

    const int NK = I_DIM / BK; // 128
    for (int kt = 0; kt < NK; ++kt) {
        const int buf = kt & 1;
        const bool more = (kt + 1) < NK;
        if (more) {
            const __half* pa = gA + (size_t)(kt + 1) * BK;
            const __half* pb = gB + (size_t)(kt + 1) * BK;
            ra0 = *(const uint4*)(pa + (size_t)lr * I_DIM + lc);
            ra1 = *(const uint4*)(pa + (size_t)(lr + 64) * I_DIM + lc);
            rb0 = *(const uint4*)(pb + (size_t)lr * I_DIM + lc);
            rb1 = *(const uint4*)(pb + (size_t)(lr + 64) * I_DIM + lc);
        }
#pragma unroll
        for (int ks = 0; ks < 2; ++ks) {
            uint32_t afr[4][4], bfr[4][2];
#pragma unroll
            for (int mi = 0; mi < 4; ++mi) {
                uint32_t ad = smem_u32(
                    &As[buf][wm * 64 + mi * 16 + (lane & 15)][ks * 16 + (lane >> 4) * 8]);
                ldsm_x4(afr[mi], ad);
            }
#pragma unroll
            for (int ni = 0; ni < 4; ++ni) {
                int l16 = lane & 15;
                uint32_t bd = smem_u32(
                    &Bs[buf][wn * 32 + ni * 8 + (l16 & 7)][ks * 16 + (l16 >> 3) * 8]);
                ldsm_x2(bfr[ni], bd);
            }
#pragma unroll
            for (int mi = 0; mi < 4; ++mi)
#pragma unroll
                for (int ni = 0; ni < 4; ++ni)
                    mma_16816(acc[mi][ni], afr[mi], bfr[ni]);
        }
        if (more) {
            const int nb = buf ^ 1;
            *(uint4*)(&As[nb][lr][lc])      = ra0;
            *(uint4*)(&As[nb][lr + 64][lc]) = ra1;
            *(uint4*)(&Bs[nb][lr][lc])      = rb0;
            *(uint4*)(&Bs[nb][lr + 64][lc]) = rb1;
            __syncthreads();
        }
    }

    // Epilogue: mma C-fragment layout -> global, fused bias add.
    const int gid = lane >> 2, tig = lane & 3;
#pragma unroll
    for (int mi = 0; mi < 4; ++mi) {
        const size_t row = bmOff + wm * 64 + mi * 16 + gid;
#pragma unroll
        for (int ni = 0; ni < 4; ++ni) {
            const int col = (int)bnOff + wn * 32 + ni * 8 + tig * 2;
            float2 bv = *(const float2*)(bias + col);
            float2 o0 = make_float2(acc[mi][ni][0] + bv.x, acc[mi][ni][1] + bv.y);
            float2 o1 = make_float2(acc[mi][ni][2] + bv.x, acc[mi][ni][3] + bv.y);
            *(float2*)(y + row * O_DIM + col)       = o0;
            *(float2*)(y + (row + 8) * O_DIM + col) = o1;
        }
    }
}

// ---------------------------------------------------------------------------
extern "C" void kernel_launch(void* const* d_in, const int* in_sizes, int n_in,
                              void* d_out, int out_size) {
    const float* x      = (const float*)d_in[0];
    const int*   q      = (const int*)d_in[1];
    const float* scales = (const float*)d_in[2];
    const float* up     = (const float*)d_in[3];
    const float* down   = (const float*)d_in[4];
    const float* alpha  = (const float*)d_in[5];
    const float* bias   = (const float*)d_in[6];
    float* y = (float*)d_out;
    (void)in_sizes; (void)n_in; (void)out_size;

    // 1) x -> fp16 (2M threads, 4 elems each)
    cvt_x_kernel<<<(T_DIM * I_DIM / 4) / 256, 256>>>(x);
    // 2) dequant + LoRA -> fp16 W ((I/4)*(O/8) threads)
    prep_w_kernel<<<((I_DIM / 4) * (O_DIM / 8)) / 256, 256>>>(q, scales, up, down, alpha);
    // 3) fp16 tensor-core GEMM + bias
    dim3 grid(O_DIM / BN, T_DIM / BM);
    gemm_kernel<<<grid, 256>>>(bias, y);
}

// round 9
// speedup vs baseline: 1.2629x; 1.2629x over previous
#include <cuda_runtime.h>
#include <cuda_fp16.h>
#include <cstdint>

// Problem dims (fixed by the dataset)
#define T_DIM 2048
#define O_DIM 4096
#define I_DIM 4096
#define R_DIM 16
#define QB    32

// Scratch: fp16 copies of W (dequant + LoRA folded) and x.
__device__ __align__(16) __half g_Wh[(size_t)O_DIM * I_DIM]; // 32 MB
__device__ __align__(16) __half g_Xh[(size_t)T_DIM * I_DIM]; // 16 MB

// ---------------------------------------------------------------------------
// Kernel 1: x (fp32) -> fp16   (8 elems / thread)
// ---------------------------------------------------------------------------
__global__ void cvt_x_kernel(const float* __restrict__ x) {
    size_t i = ((size_t)blockIdx.x * blockDim.x + threadIdx.x) * 8;
    float4 v0 = *(const float4*)(x + i);
    float4 v1 = *(const float4*)(x + i + 4);
    *(__half2*)(g_Xh + i)     = __floats2half2_rn(v0.x, v0.y);
    *(__half2*)(g_Xh + i + 2) = __floats2half2_rn(v0.z, v0.w);
    *(__half2*)(g_Xh + i + 4) = __floats2half2_rn(v1.x, v1.y);
    *(__half2*)(g_Xh + i + 6) = __floats2half2_rn(v1.z, v1.w);
}

// ---------------------------------------------------------------------------
// Kernel 2: W_fp16[o,i] = (q-8)*scale + alpha * up@down
// ---------------------------------------------------------------------------
__global__ void prep_w_kernel(const int* __restrict__ q,
                              const float* __restrict__ scales,
                              const float* __restrict__ up,
                              const float* __restrict__ down,
                              const float* __restrict__ alpha_p) {
    const int igroups = I_DIM / 4; // 1024
    size_t gt = (size_t)blockIdx.x * blockDim.x + threadIdx.x;
    int ig = (int)(gt % igroups);
    int ob = (int)(gt / igroups) * 8;
    int i  = ig * 4;
    float alpha = *alpha_p;

    float4 dsum[8];
#pragma unroll
    for (int j = 0; j < 8; ++j) dsum[j] = make_float4(0.f, 0.f, 0.f, 0.f);

#pragma unroll
    for (int r = 0; r < R_DIM; ++r) {
        float4 dv = *(const float4*)(down + (size_t)r * I_DIM + i);
#pragma unroll
        for (int j = 0; j < 8; ++j) {
            float u = up[(size_t)(ob + j) * R_DIM + r];
            dsum[j].x += u * dv.x;
            dsum[j].y += u * dv.y;
            dsum[j].z += u * dv.z;
            dsum[j].w += u * dv.w;
        }
    }

#pragma unroll
    for (int j = 0; j < 8; ++j) {
        int o = ob + j;
        size_t base = (size_t)o * I_DIM + i;
        int4 qv = *(const int4*)(q + base);
        float s = scales[(size_t)o * (I_DIM / QB) + (i >> 5)];
        float w0 = (float)(qv.x - 8) * s + alpha * dsum[j].x;
        float w1 = (float)(qv.y - 8) * s + alpha * dsum[j].y;
        float w2 = (float)(qv.z - 8) * s + alpha * dsum[j].z;
        float w3 = (float)(qv.w - 8) * s + alpha * dsum[j].w;
        *(__half2*)(g_Wh + base)     = __floats2half2_rn(w0, w1);
        *(__half2*)(g_Wh + base + 2) = __floats2half2_rn(w2, w3);
    }
}

// ---------------------------------------------------------------------------
// Kernel 3: GEMM  y[t,o] = sum_k Xh[t,k]*Wh[o,k] + bias[o]
// CTA tile 128x256x64, 8 warps (2M x 4N), warp tile 64x64.
// 3-stage cp.async pipeline (wait_group 1), one __syncthreads per k-tile.
// mma.sync m16n8k16 f16->f32; ldmatrix x4 for both A and B; padded smem
// rows of 72 halves (144B: stride -> bank step 4 -> conflict-free ldsm).
// ---------------------------------------------------------------------------
#define GBM 128
#define GBN 256
#define GBK 64
#define NKT (I_DIM / GBK)        // 64
#define LDSH 72                  // halves per smem row (144 B)
#define A_STAGE_H (GBM * LDSH)   // 9216 halves = 18 KB
#define B_STAGE_H (GBN * LDSH)   // 18432 halves = 36 KB
#define STAGE_H   (A_STAGE_H + B_STAGE_H)
#define NSTAGE 3
#define DYN_SMEM_BYTES (NSTAGE * STAGE_H * 2)  // 162 KB

__device__ __forceinline__ uint32_t smem_u32(const void* p) {
    return (uint32_t)__cvta_generic_to_shared(p);
}
__device__ __forceinline__ void cp_async16(uint32_t s, const void* g) {
    asm volatile("cp.async.cg.shared.global [%0], [%1], 16;" :: "r"(s), "l"(g));
}
__device__ __forceinline__ void ldsm_x4(uint32_t* r, uint32_t addr) {
    asm volatile("ldmatrix.sync.aligned.m8n8.x4.shared.b16 {%0,%1,%2,%3}, [%4];"
                 : "=r"(r[0]), "=r"(r[1]), "=r"(r[2]), "=r"(r[3]) : "r"(addr));
}
__device__ __forceinline__ void mma_16816(float* c, const uint32_t* a, const uint32_t* b) {
    asm volatile(
        "mma.sync.aligned.m16n8k16.row.col.f32.f16.f16.f32 "
        "{%0,%1,%2,%3}, {%4,%5,%6,%7}, {%8,%9}, {%0,%1,%2,%3};\n"
        : "+f"(c[0]), "+f"(c[1]), "+f"(c[2]), "+f"(c[3])
        : "r"(a[0]), "r"(a[1]), "r"(a[2]), "r"(a[3]), "r"(b[0]), "r"(b[1]));
}

__global__ void __launch_bounds__(256, 1) gemm_kernel(const float* __restrict__ bias,
                                                      float* __restrict__ y) {
    extern __shared__ __half smem[];

    const int tid  = threadIdx.x;
    const int lane = tid & 31;
    const int warp = tid >> 5;
    const int wm = warp >> 2;  // 0..1 (M)
    const int wn = warp & 3;   // 0..3 (N)

    const size_t bmOff = (size_t)blockIdx.y * GBM;  // T rows
    const size_t bnOff = (size_t)blockIdx.x * GBN;  // O cols
    const __half* gA = g_Xh + bmOff * I_DIM;
    const __half* gB = g_Wh + bnOff * I_DIM;

    // Per-thread load slots: A 4 chunks, B 8 chunks of 16B per k-tile.
    const int arow[4] = { (tid + 0)   >> 3, (tid + 256) >> 3,
                          (tid + 512) >> 3, (tid + 768) >> 3 };
    const int ach = (tid & 7) * 8;  // half offset within 64-half row

    auto issue_stage = [&](int kt, int stg) {
        __half* sa = smem + stg * STAGE_H;
        __half* sb = sa + A_STAGE_H;
        const __half* gAk = gA + kt * GBK;
        const __half* gBk = gB + kt * GBK;
#pragma unroll
        for (int j = 0; j < 4; ++j) {
            int row = arow[j];
            cp_async16(smem_u32(sa + row * LDSH + ach),
                       gAk + (size_t)row * I_DIM + ach);
        }
#pragma unroll
        for (int j = 0; j < 8; ++j) {
            int c = tid + j * 256;
            int row = c >> 3;
            cp_async16(smem_u32(sb + row * LDSH + ach),
                       gBk + (size_t)row * I_DIM + ach);
        }
    };

    float acc[4][8][4];
#pragma unroll
    for (int a = 0; a < 4; ++a)
#pragma unroll
        for (int b = 0; b < 8; ++b)
#pragma unroll
            for (int c = 0; c < 4; ++c) acc[a][b][c] = 0.f;

    // prologue: stages 0,1
    issue_stage(0, 0);
    asm volatile("cp.async.commit_group;" ::: "memory");
    issue_stage(1, 1);
    asm volatile("cp.async.commit_group;" ::: "memory");

    // Precomputed ldsm lane addressing
    const int a_r = (lane & 15);          // row within 16
    const int a_c = (lane >> 4) * 8;      // 0 or 8 halves
    const int bg  = lane >> 3;            // 0..3
    const int b_r = ((bg >> 1) * 8) + (lane & 7);  // row within 16
    const int b_c = (bg & 1) * 8;         // 0 or 8 halves

    for (int kt = 0; kt < NKT; ++kt) {
        const int stg = kt % NSTAGE;
        asm volatile("cp.async.wait_group 1;" ::: "memory");
        __syncthreads();

        if (kt + 2 < NKT) issue_stage(kt + 2, (kt + 2) % NSTAGE);
        asm volatile("cp.async.commit_group;" ::: "memory");

        const __half* sa = smem + stg * STAGE_H;
        const __half* sb = sa + A_STAGE_H;
#pragma unroll
        for (int ks = 0; ks < 4; ++ks) {
            uint32_t afr[4][4], bfr[8][2];
#pragma unroll
            for (int mi = 0; mi < 4; ++mi) {
                uint32_t ad = smem_u32(sa + (wm * 64 + mi * 16 + a_r) * LDSH
                                          + ks * 16 + a_c);
                ldsm_x4(afr[mi], ad);
            }
#pragma unroll
            for (int nq = 0; nq < 4; ++nq) {
                uint32_t r[4];
                uint32_t bd = smem_u32(sb + (wn * 64 + nq * 16 + b_r) * LDSH
                                          + ks * 16 + b_c);
                ldsm_x4(r, bd);
                bfr[nq * 2 + 0][0] = r[0]; bfr[nq * 2 + 0][1] = r[1];
                bfr[nq * 2 + 1][0] = r[2]; bfr[nq * 2 + 1][1] = r[3];
            }
#pragma unroll
            for (int mi = 0; mi < 4; ++mi)
#pragma unroll
                for (int ni = 0; ni < 8; ++ni)
                    mma_16816(acc[mi][ni], afr[mi], bfr[ni]);
        }
    }

    // Epilogue: fused bias add, float2 stores.
    const int gid = lane >> 2, tig = lane & 3;
#pragma unroll
    for (int mi = 0; mi < 4; ++mi) {
        const size_t row = bmOff + wm * 64 + mi * 16 + gid;
#pragma unroll
        for (int ni = 0; ni < 8; ++ni) {
            const int col = (int)bnOff + wn * 64 + ni * 8 + tig * 2;
            float2 bv = *(const float2*)(bias + col);
            float2 o0 = make_float2(acc[mi][ni][0] + bv.x, acc[mi][ni][1] + bv.y);
            float2 o1 = make_float2(acc[mi][ni][2] + bv.x, acc[mi][ni][3] + bv.y);
            *(float2*)(y + row * O_DIM + col)       = o0;
            *(float2*)(y + (row + 8) * O_DIM + col) = o1;
        }
    }
}

// ---------------------------------------------------------------------------
extern "C" void kernel_launch(void* const* d_in, const int* in_sizes, int n_in,
                              void* d_out, int out_size) {
    const float* x      = (const float*)d_in[0];
    const int*   q      = (const int*)d_in[1];
    const float* scales = (const float*)d_in[2];
    const float* up     = (const float*)d_in[3];
    const float* down   = (const float*)d_in[4];
    const float* alpha  = (const float*)d_in[5];
    const float* bias   = (const float*)d_in[6];
    float* y = (float*)d_out;
    (void)in_sizes; (void)n_in; (void)out_size;

    // 1) x -> fp16
    cvt_x_kernel<<<(T_DIM * I_DIM / 8) / 256, 256>>>(x);
    // 2) dequant + LoRA -> fp16 W
    prep_w_kernel<<<((I_DIM / 4) * (O_DIM / 8)) / 256, 256>>>(q, scales, up, down, alpha);
    // 3) fp16 tensor-core GEMM + bias
    cudaFuncSetAttribute(gemm_kernel, cudaFuncAttributeMaxDynamicSharedMemorySize,
                         DYN_SMEM_BYTES);
    dim3 grid(O_DIM / GBN, T_DIM / GBM);  // (16, 16)
    gemm_kernel<<<grid, 256, DYN_SMEM_BYTES>>>(bias, y);
}